// round 10
// baseline (speedup 1.0000x reference)
#include <cuda_runtime.h>
#include <cstdint>

// Problem constants
#define Bx 256
#define Tx 3000
#define Ix 40
#define Hx 64
#define Gx 256        // 4*H gates
#define RCH 8         // recurrent x_proj chunk steps (3000 % 8 == 0 -> 375 chunks)
#define XTK 50        // xproj tokens per block tile (3000 % 50 == 0)

// Scratch (allocation-free rule: __device__ globals)
__device__ float g_h[2][(size_t)Bx * Tx * Hx];    // per-direction hidden outputs
__device__ float g_xp[2][(size_t)Bx * Tx * Gx];   // input projections (+biases); dir1 time-reversed

// ---------- packed f32x2 helpers ----------
union F2U { float2 f; unsigned long long u; };

__device__ __forceinline__ void ffma2(unsigned long long& acc,
                                      unsigned long long a,
                                      unsigned long long b) {
    asm("fma.rn.f32x2 %0, %1, %2, %0;" : "+l"(acc) : "l"(a), "l"(b));
}
__device__ __forceinline__ unsigned long long fadd2(unsigned long long a, unsigned long long b) {
    unsigned long long r;
    asm("add.rn.f32x2 %0, %1, %2;" : "=l"(r) : "l"(a), "l"(b));
    return r;
}
__device__ __forceinline__ float fsigmoid(float x) {
    return __fdividef(1.0f, 1.0f + __expf(-x));
}
__device__ __forceinline__ float ftanh_fast(float x) {
    return 1.0f - __fdividef(2.0f, __expf(2.0f * x) + 1.0f);
}
__device__ __forceinline__ float hsum2(unsigned long long a, unsigned long long b) {
    F2U s; s.u = fadd2(a, b);
    return s.f.x + s.f.y;
}

// ---------- cp.async helpers ----------
__device__ __forceinline__ unsigned int smem_u32(const void* p) {
    return (unsigned int)__cvta_generic_to_shared(p);
}
__device__ __forceinline__ void cp_async16(unsigned int s, const void* g) {
    asm volatile("cp.async.cg.shared.global [%0], [%1], 16;" :: "r"(s), "l"(g));
}
#define CP_COMMIT() asm volatile("cp.async.commit_group;")
#define CP_WAIT1()  asm volatile("cp.async.wait_group 1;")

// ================= x-projection kernel =================
// Both directions per block (R5 version, measured 822us). Thread g holds
// W_ih rows for dir0/dir1; x tile read once from SMEM as LDS.128 broadcasts.
// dir1 output stored time-reversed.
__global__ __launch_bounds__(256, 2)
void xproj_kernel(const float* __restrict__ x,
                  const float* __restrict__ WihF, const float* __restrict__ bihF,
                  const float* __restrict__ bhhF,
                  const float* __restrict__ WihB, const float* __restrict__ bihB,
                  const float* __restrict__ bhhB)
{
    const int g = threadIdx.x;
    __shared__ __align__(16) float sx[XTK * Ix];   // 8 KB

    unsigned long long wf[20], wb[20];
    {
        const float2* wrf = (const float2*)(WihF + (size_t)g * Ix);
        const float2* wrb = (const float2*)(WihB + (size_t)g * Ix);
        #pragma unroll
        for (int j = 0; j < 20; j++) { F2U u; u.f = wrf[j]; wf[j] = u.u; }
        #pragma unroll
        for (int j = 0; j < 20; j++) { F2U u; u.f = wrb[j]; wb[j] = u.u; }
    }
    const float biasF = bihF[g] + bhhF[g];
    const float biasB = bihB[g] + bhhB[g];

    const int tiles_per_b = Tx / XTK;
    const int batch = blockIdx.x / tiles_per_b;
    const int trel  = (blockIdx.x % tiles_per_b) * XTK;

    {
        const float4* xs = (const float4*)(x + ((size_t)batch * Tx + trel) * Ix);
        float4* sd = (float4*)sx;
        #pragma unroll
        for (int i = 0; i < 2; i++) {
            int idx = threadIdx.x + i * 256;
            if (idx < XTK * Ix / 4) sd[idx] = xs[idx];
        }
    }
    __syncthreads();

    float* pF = g_xp[0] + ((size_t)batch * Tx + trel) * Gx + g;
    float* pB = g_xp[1] + ((size_t)batch * Tx + (Tx - 1 - trel)) * Gx + g;
    const ulonglong2* xr = (const ulonglong2*)sx;

    #pragma unroll 1
    for (int k = 0; k < XTK / 2; k++) {
        F2U fa0, fa1, ba0, ba1, fb0, fb1, bb0, bb1;
        fa0.f = make_float2(biasF, 0.0f); fa1.f = make_float2(0.0f, 0.0f);
        ba0.f = make_float2(biasB, 0.0f); ba1.f = make_float2(0.0f, 0.0f);
        fb0 = fa0; fb1 = fa1; bb0 = ba0; bb1 = ba1;
        #pragma unroll
        for (int j = 0; j < 10; j++) {
            const ulonglong2 ua = xr[j];            // token 2k
            const ulonglong2 ub = xr[10 + j];       // token 2k+1
            ffma2(fa0.u, ua.x, wf[2 * j]);  ffma2(fa1.u, ua.y, wf[2 * j + 1]);
            ffma2(ba0.u, ua.x, wb[2 * j]);  ffma2(ba1.u, ua.y, wb[2 * j + 1]);
            ffma2(fb0.u, ub.x, wf[2 * j]);  ffma2(fb1.u, ub.y, wf[2 * j + 1]);
            ffma2(bb0.u, ub.x, wb[2 * j]);  ffma2(bb1.u, ub.y, wb[2 * j + 1]);
        }
        xr += 20;
        pF[0]   = hsum2(fa0.u, fa1.u);
        pF[Gx]  = hsum2(fb0.u, fb1.u);
        pB[0]   = hsum2(ba0.u, ba1.u);
        pB[-Gx] = hsum2(bb0.u, bb1.u);
        pF += 2 * Gx;
        pB -= 2 * Gx;
    }
}

// ================= recurrent LSTM kernel =================
// Gate-pair split for 32 warps/SM: 512 threads/block, thread = (gate g,
// h-half) holding 32 weight floats (16 u64 regs). Pair combine = shfl_xor(1).
// Structure otherwise identical to the proven R3 kernel: 2 seqs/block,
// sgates SMEM exchange, 2 barriers/step, R3 cp.async double-buffering.
__global__ __launch_bounds__(512, 2)
void lstm_kernel(const float* __restrict__ Whh_f, const float* __restrict__ Whh_b)
{
    const int dir   = blockIdx.x >> 7;          // 0..127 fwd, 128..255 bwd
    const int bbase = (blockIdx.x & 127) * 2;   // batches bbase, bbase+1

    const float* Whh = dir ? Whh_b : Whh_f;
    float* hout = g_h[dir];
    const float* xpd = g_xp[dir];

    const int tid  = threadIdx.x;
    const int g    = tid >> 1;                  // gate 0..255
    const int half = tid & 1;                   // h-half 0/1
    const int region = g >> 6;                  // warp-uniform gate type (2 = tanh)

    __shared__ __align__(16) float sxp[2][2][RCH * Gx];  // [seq][buf] 32 KB
    __shared__ __align__(16) float sh[2][Hx];            // current h, both seqs
    __shared__ float sgates[2][Gx];

    // half of W_hh row g: 32 floats = 16 u64 regs
    // whh[j] covers W_hh[g][half*32 + 2j .. half*32 + 2j+1]
    unsigned long long whh[16];
    {
        const float2* wr = (const float2*)(Whh + (size_t)g * Hx + half * 32);
        #pragma unroll
        for (int j = 0; j < 16; j++) { F2U a; a.f = wr[j]; whh[j] = a.u; }
    }

    if (tid < 128) sh[tid >> 6][tid & 63] = 0.0f;
    float c = 0.0f;                             // phase-2 state (tid < 128)

    // cp.async slice: 256 threads per seq, 32B each (chunk = 8KB/seq)
    const int cseq = tid >> 8;
    const char* xsrc = (const char*)(xpd + (size_t)(bbase + cseq) * Tx * Gx) + (tid & 255) * 32;
    const unsigned int sbase = smem_u32(&sxp[cseq][0][0]) + (tid & 255) * 32;
    const unsigned int SBUF = (unsigned int)(RCH * Gx * 4);  // 8192 (buf stride within seq)
    const int CHBYTES = RCH * Gx * 4;

    // phase-2 output pointer (tid<128): (seq s, idx u)
    float* hptr = hout + ((size_t)(bbase + (tid >> 6)) * Tx + (dir ? (Tx - 1) : 0)) * Hx + (tid & 63);
    const ptrdiff_t hstep = dir ? -Hx : Hx;

    // prefetch chunk 0 into buffer 0
    cp_async16(sbase, xsrc);
    cp_async16(sbase + 16, xsrc + 16);
    CP_COMMIT();

    const int NCH = Tx / RCH;
    for (int ck = 0; ck < NCH; ck++) {
        // prefetch ck+1; commit; wait for ck; barrier (R3-proven pattern)
        if (ck + 1 < NCH) {
            const unsigned int sdst = sbase + ((ck + 1) & 1) * SBUF;
            const char* gsrc = xsrc + (size_t)(ck + 1) * CHBYTES;
            cp_async16(sdst, gsrc);
            cp_async16(sdst + 16, gsrc + 16);
        }
        CP_COMMIT();
        CP_WAIT1();
        __syncthreads();

        const float* xbA = sxp[0][ck & 1];
        const float* xbB = sxp[1][ck & 1];

        #pragma unroll 1
        for (int si = 0; si < RCH; si++) {
            // ---- phase 1: half-dot for gate g, both seqs ----
            const float xvA = xbA[si * Gx + g];
            const float xvB = xbB[si * Gx + g];

            F2U aA0, aA1, aB0, aB1;
            aA0.f = make_float2(0.0f, 0.0f);
            aA1 = aA0; aB0 = aA0; aB1 = aA0;

            // this thread's h-half: floats [half*32, half*32+32) = 8 ulonglong2
            const ulonglong2* hA = (const ulonglong2*)sh[0] + half * 8;
            const ulonglong2* hB = (const ulonglong2*)sh[1] + half * 8;
            #pragma unroll
            for (int k = 0; k < 8; k++) {
                const ulonglong2 ua = hA[k];   // floats half*32 + 4k .. +3
                const ulonglong2 ub = hB[k];
                ffma2(aA0.u, ua.x, whh[2 * k]);
                ffma2(aA1.u, ua.y, whh[2 * k + 1]);
                ffma2(aB0.u, ub.x, whh[2 * k]);
                ffma2(aB1.u, ub.y, whh[2 * k + 1]);
            }
            float vA = hsum2(aA0.u, aA1.u);
            float vB = hsum2(aB0.u, aB1.u);
            vA += __shfl_xor_sync(0xffffffffu, vA, 1);   // combine halves (adjacent lanes)
            vB += __shfl_xor_sync(0xffffffffu, vB, 1);
            vA += xvA;
            vB += xvB;

            const float aA = (region == 2) ? ftanh_fast(vA) : fsigmoid(vA);
            const float aB = (region == 2) ? ftanh_fast(vB) : fsigmoid(vB);
            if (half == 0) {
                sgates[0][g] = aA;
                sgates[1][g] = aB;
            }
            __syncthreads();

            // ---- phase 2: c/h update (tid < 128: seq = tid>>6, u = tid&63) ----
            if (tid < 128) {
                const int s = tid >> 6;
                const int u = tid & 63;
                const float ig = sgates[s][u];
                const float fg = sgates[s][64 + u];
                const float gg = sgates[s][128 + u];
                const float og = sgates[s][192 + u];
                c = fg * c + ig * gg;
                const float h = og * ftanh_fast(c);
                sh[s][u] = h;
                *hptr = h;
                hptr += hstep;
            }
            __syncthreads();
        }
    }
}

// ================= MLP head kernel =================
// 2 lanes per token (hf/hb halves), shfl-combine per output unit.
__global__ __launch_bounds__(256, 2)
void head_kernel(const float* __restrict__ W1, const float* __restrict__ b1,
                 const float* __restrict__ W2, const float* __restrict__ b2,
                 float* __restrict__ out)
{
    __shared__ __align__(16) float sW1[64 * 128];  // 32 KB
    __shared__ float sb1[64];
    __shared__ float sW2[64];

    const int tid = threadIdx.x;
    for (int i = tid; i < 64 * 128 / 4; i += 256)
        ((float4*)sW1)[i] = ((const float4*)W1)[i];
    if (tid < 64) { sb1[tid] = b1[tid]; sW2[tid] = W2[tid]; }
    __syncthreads();
    const float bias2 = b2[0];

    const size_t tok = (size_t)blockIdx.x * 128 + (tid >> 1);
    const int hsel = tid & 1;

    unsigned long long hreg[32];
    {
        const ulonglong2* hv = (const ulonglong2*)(g_h[hsel] + tok * Hx);
        #pragma unroll
        for (int j = 0; j < 16; j++) {
            ulonglong2 u = hv[j];
            hreg[2 * j] = u.x; hreg[2 * j + 1] = u.y;
        }
    }

    float acc = bias2;
    #pragma unroll 4
    for (int o = 0; o < 64; o++) {
        const unsigned long long* w =
            (const unsigned long long*)(sW1 + o * 128 + hsel * 64);
        F2U a0, a1, a2, a3;
        a0.f = make_float2(0.0f, 0.0f);
        a1 = a0; a2 = a0; a3 = a0;
        #pragma unroll
        for (int j = 0; j < 8; j++) {
            ffma2(a0.u, hreg[j],      w[j]);
            ffma2(a1.u, hreg[8 + j],  w[8 + j]);
            ffma2(a2.u, hreg[16 + j], w[16 + j]);
            ffma2(a3.u, hreg[24 + j], w[24 + j]);
        }
        F2U sx; sx.u = fadd2(fadd2(a0.u, a1.u), fadd2(a2.u, a3.u));
        float v = sx.f.x + sx.f.y;
        v += __shfl_xor_sync(0xffffffffu, v, 1);
        const float z = fmaxf(v + sb1[o], 0.0f);
        acc = fmaf(z, sW2[o], acc);
    }
    if (hsel == 0) out[tok] = fsigmoid(acc);
}

// ================= launch =================
extern "C" void kernel_launch(void* const* d_in, const int* in_sizes, int n_in,
                              void* d_out, int out_size)
{
    const float* x     = (const float*)d_in[0];
    const float* Wih_f = (const float*)d_in[1];
    const float* Whh_f = (const float*)d_in[2];
    const float* bih_f = (const float*)d_in[3];
    const float* bhh_f = (const float*)d_in[4];
    const float* Wih_b = (const float*)d_in[5];
    const float* Whh_b = (const float*)d_in[6];
    const float* bih_b = (const float*)d_in[7];
    const float* bhh_b = (const float*)d_in[8];
    const float* W1    = (const float*)d_in[9];
    const float* b1    = (const float*)d_in[10];
    const float* W2    = (const float*)d_in[11];
    const float* b2    = (const float*)d_in[12];
    float* out = (float*)d_out;

    xproj_kernel<<<Bx * (Tx / XTK), 256>>>(x, Wih_f, bih_f, bhh_f, Wih_b, bih_b, bhh_b);
    lstm_kernel<<<2 * 128, 512>>>(Whh_f, Whh_b);   // gate-pair split, 32 warps/SM
    head_kernel<<<(Bx * Tx) / 128, 256>>>(W1, b1, W2, b2, out);
}

// round 11
// speedup vs baseline: 1.3098x; 1.3098x over previous
#include <cuda_runtime.h>
#include <cstdint>

// Problem constants
#define Bx 256
#define Tx 3000
#define Ix 40
#define Hx 64
#define Gx 256        // 4*H gates
#define RCH 8         // recurrent chunk steps (3000 % 8 == 0 -> 375 chunks)

// Scratch (allocation-free rule: __device__ globals)
__device__ float g_h[2][(size_t)Bx * Tx * Hx];    // per-direction hidden outputs

// ---------- packed f32x2 helpers ----------
union F2U { float2 f; unsigned long long u; };

__device__ __forceinline__ void ffma2(unsigned long long& acc,
                                      unsigned long long a,
                                      unsigned long long b) {
    asm("fma.rn.f32x2 %0, %1, %2, %0;" : "+l"(acc) : "l"(a), "l"(b));
}
__device__ __forceinline__ unsigned long long fadd2(unsigned long long a, unsigned long long b) {
    unsigned long long r;
    asm("add.rn.f32x2 %0, %1, %2;" : "=l"(r) : "l"(a), "l"(b));
    return r;
}
__device__ __forceinline__ float fsigmoid(float x) {
    return __fdividef(1.0f, 1.0f + __expf(-x));
}
__device__ __forceinline__ float ftanh_fast(float x) {
    return 1.0f - __fdividef(2.0f, __expf(2.0f * x) + 1.0f);
}
__device__ __forceinline__ float hsum2(unsigned long long a, unsigned long long b) {
    F2U s; s.u = fadd2(a, b);
    return s.f.x + s.f.y;
}

// ---------- cp.async helpers ----------
__device__ __forceinline__ unsigned int smem_u32(const void* p) {
    return (unsigned int)__cvta_generic_to_shared(p);
}
__device__ __forceinline__ void cp_async16(unsigned int s, const void* g) {
    asm volatile("cp.async.cg.shared.global [%0], [%1], 16;" :: "r"(s), "l"(g));
}
#define CP_COMMIT() asm volatile("cp.async.commit_group;")
#define CP_WAIT1()  asm volatile("cp.async.wait_group 1;")

// ================= fused LSTM kernel (input projection inlined) =================
// Exactly the R3 structure (proven fastest recurrence): 256 blocks, 256 threads,
// 2 blocks/SM, thread g = gate g for the block's 2 sequences, W_hh row in regs,
// sgates SMEM exchange, 2 barriers/step, R3 cp.async double-buffer.
// NEW: x@W_ih computed in-loop from raw x (W_ih row + bias in regs), deleting
// the separate xproj kernel and its 3.1 GB g_xp DRAM round-trip.
__global__ __launch_bounds__(256, 2)
void lstm_fused_kernel(const float* __restrict__ x,
                       const float* __restrict__ WihF, const float* __restrict__ WhhF,
                       const float* __restrict__ bihF, const float* __restrict__ bhhF,
                       const float* __restrict__ WihB, const float* __restrict__ WhhB,
                       const float* __restrict__ bihB, const float* __restrict__ bhhB)
{
    const int dir   = blockIdx.x & 1;
    const int bpair = blockIdx.x >> 1;          // 0..127
    const int bA    = 2 * bpair;                // batches bA, bA+1

    const float* Whh = dir ? WhhB : WhhF;
    const float* Wih = dir ? WihB : WihF;
    float* hout = g_h[dir];

    const int g = threadIdx.x;
    const int region = g >> 6;                  // warp-uniform gate type (2 = tanh)

    __shared__ __align__(16) float sx[2][2][RCH * Ix];   // [seq][buf] x chunks, 5 KB
    __shared__ __align__(16) float sh[2][Hx];
    __shared__ float sgates[2][Gx];

    // W_hh row (64 floats = 32 u64) + W_ih row (40 floats = 20 u64) + bias
    unsigned long long whh[32], wih[20];
    {
        const float2* wr = (const float2*)(Whh + (size_t)g * Hx);
        #pragma unroll
        for (int j = 0; j < 32; j++) { F2U a; a.f = wr[j]; whh[j] = a.u; }
        const float2* wi = (const float2*)(Wih + (size_t)g * Ix);
        #pragma unroll
        for (int j = 0; j < 20; j++) { F2U a; a.f = wi[j]; wih[j] = a.u; }
    }
    const float bias = dir ? (bihB[g] + bhhB[g]) : (bihF[g] + bhhF[g]);

    if (g < 128) sh[g >> 6][g & 63] = 0.0f;
    float c = 0.0f;                             // phase-2 state (g < 128)

    // cp.async: chunk = RCH steps x 40 floats = 1280B per seq (contiguous for
    // both directions: bwd chunk ck covers [Tx-RCH-ck*RCH, ...+RCH)).
    // threads 0..159: seq = t/80, 16B segment (t%80)*16.
    const int cth  = (threadIdx.x < 160);
    const int cseq = threadIdx.x / 80;          // valid when cth
    const int coff = (threadIdx.x % 80) * 16;
    const char* xbase = (const char*)(x + (size_t)(bA + (cseq & 1)) * Tx * Ix) + coff;
    const unsigned int sb0 = smem_u32(&sx[cseq & 1][0][0]) + coff;
    const unsigned int sb1 = smem_u32(&sx[cseq & 1][1][0]) + coff;
    const int ROWB = Ix * 4;                    // 160 bytes per timestep

    // phase-2 output pointer (g<128): (seq s = g>>6, idx u = g&63)
    float* hptr = hout + ((size_t)(bA + (g >> 6)) * Tx + (dir ? (Tx - 1) : 0)) * Hx + (g & 63);
    const ptrdiff_t hstep = dir ? -Hx : Hx;

    // chunk ck's first (lowest) timestep
    auto tlo = [&](int ck) { return dir ? (Tx - RCH - ck * RCH) : (ck * RCH); };

    // prefetch chunk 0 into buffer 0
    if (cth) cp_async16(sb0, xbase + (size_t)tlo(0) * ROWB);
    CP_COMMIT();

    const int NCH = Tx / RCH;
    for (int ck = 0; ck < NCH; ck++) {
        // prefetch ck+1; commit; wait for ck; barrier (R3-proven pattern)
        if (ck + 1 < NCH) {
            if (cth) {
                const unsigned int sdst = ((ck + 1) & 1) ? sb1 : sb0;
                cp_async16(sdst, xbase + (size_t)tlo(ck + 1) * ROWB);
            }
        }
        CP_COMMIT();
        CP_WAIT1();
        __syncthreads();

        const float* xcA = sx[0][ck & 1];
        const float* xcB = sx[1][ck & 1];

        #pragma unroll 1
        for (int si = 0; si < RCH; si++) {
            const int li = dir ? (RCH - 1 - si) : si;   // row within chunk

            // ---- phase 1: full gate pre-activation (x-proj + h-proj) ----
            F2U aA0, aA1, aB0, aB1;
            aA0.f = make_float2(bias, 0.0f);
            aB0 = aA0;
            aA1.f = make_float2(0.0f, 0.0f);
            aB1 = aA1;

            const ulonglong2* xrA = (const ulonglong2*)(xcA + li * Ix);
            const ulonglong2* xrB = (const ulonglong2*)(xcB + li * Ix);
            #pragma unroll
            for (int j = 0; j < 10; j++) {
                const ulonglong2 ua = xrA[j];
                const ulonglong2 ub = xrB[j];
                ffma2(aA0.u, ua.x, wih[2 * j]);
                ffma2(aA1.u, ua.y, wih[2 * j + 1]);
                ffma2(aB0.u, ub.x, wih[2 * j]);
                ffma2(aB1.u, ub.y, wih[2 * j + 1]);
            }

            const ulonglong2* hA = (const ulonglong2*)sh[0];  // LDS.128 broadcast
            const ulonglong2* hB = (const ulonglong2*)sh[1];
            #pragma unroll
            for (int k = 0; k < 16; k++) {
                const ulonglong2 ua = hA[k];
                const ulonglong2 ub = hB[k];
                ffma2(aA0.u, ua.x, whh[2 * k]);
                ffma2(aA1.u, ua.y, whh[2 * k + 1]);
                ffma2(aB0.u, ub.x, whh[2 * k]);
                ffma2(aB1.u, ub.y, whh[2 * k + 1]);
            }
            const float vA = hsum2(aA0.u, aA1.u);
            const float vB = hsum2(aB0.u, aB1.u);

            if (region == 2) {
                sgates[0][g] = ftanh_fast(vA);
                sgates[1][g] = ftanh_fast(vB);
            } else {
                sgates[0][g] = fsigmoid(vA);
                sgates[1][g] = fsigmoid(vB);
            }
            __syncthreads();

            // ---- phase 2: c/h update (g < 128: seq = g>>6, u = g&63) ----
            if (g < 128) {
                const int s = g >> 6;
                const int u = g & 63;
                const float ig = sgates[s][u];
                const float fg = sgates[s][64 + u];
                const float gg = sgates[s][128 + u];
                const float og = sgates[s][192 + u];
                c = fg * c + ig * gg;
                const float h = og * ftanh_fast(c);
                sh[s][u] = h;
                *hptr = h;
                hptr += hstep;
            }
            __syncthreads();
        }
    }
}

// ================= MLP head kernel =================
// 2 lanes per token (hf/hb halves), shfl-combine per output unit.
__global__ __launch_bounds__(256, 2)
void head_kernel(const float* __restrict__ W1, const float* __restrict__ b1,
                 const float* __restrict__ W2, const float* __restrict__ b2,
                 float* __restrict__ out)
{
    __shared__ __align__(16) float sW1[64 * 128];  // 32 KB
    __shared__ float sb1[64];
    __shared__ float sW2[64];

    const int tid = threadIdx.x;
    for (int i = tid; i < 64 * 128 / 4; i += 256)
        ((float4*)sW1)[i] = ((const float4*)W1)[i];
    if (tid < 64) { sb1[tid] = b1[tid]; sW2[tid] = W2[tid]; }
    __syncthreads();
    const float bias2 = b2[0];

    const size_t tok = (size_t)blockIdx.x * 128 + (tid >> 1);
    const int hsel = tid & 1;

    unsigned long long hreg[32];
    {
        const ulonglong2* hv = (const ulonglong2*)(g_h[hsel] + tok * Hx);
        #pragma unroll
        for (int j = 0; j < 16; j++) {
            ulonglong2 u = hv[j];
            hreg[2 * j] = u.x; hreg[2 * j + 1] = u.y;
        }
    }

    float acc = bias2;
    #pragma unroll 4
    for (int o = 0; o < 64; o++) {
        const unsigned long long* w =
            (const unsigned long long*)(sW1 + o * 128 + hsel * 64);
        F2U a0, a1, a2, a3;
        a0.f = make_float2(0.0f, 0.0f);
        a1 = a0; a2 = a0; a3 = a0;
        #pragma unroll
        for (int j = 0; j < 8; j++) {
            ffma2(a0.u, hreg[j],      w[j]);
            ffma2(a1.u, hreg[8 + j],  w[8 + j]);
            ffma2(a2.u, hreg[16 + j], w[16 + j]);
            ffma2(a3.u, hreg[24 + j], w[24 + j]);
        }
        F2U sx2; sx2.u = fadd2(fadd2(a0.u, a1.u), fadd2(a2.u, a3.u));
        float v = sx2.f.x + sx2.f.y;
        v += __shfl_xor_sync(0xffffffffu, v, 1);
        const float z = fmaxf(v + sb1[o], 0.0f);
        acc = fmaf(z, sW2[o], acc);
    }
    if (hsel == 0) out[tok] = fsigmoid(acc);
}

// ================= launch =================
extern "C" void kernel_launch(void* const* d_in, const int* in_sizes, int n_in,
                              void* d_out, int out_size)
{
    const float* x     = (const float*)d_in[0];
    const float* Wih_f = (const float*)d_in[1];
    const float* Whh_f = (const float*)d_in[2];
    const float* bih_f = (const float*)d_in[3];
    const float* bhh_f = (const float*)d_in[4];
    const float* Wih_b = (const float*)d_in[5];
    const float* Whh_b = (const float*)d_in[6];
    const float* bih_b = (const float*)d_in[7];
    const float* bhh_b = (const float*)d_in[8];
    const float* W1    = (const float*)d_in[9];
    const float* b1    = (const float*)d_in[10];
    const float* W2    = (const float*)d_in[11];
    const float* b2    = (const float*)d_in[12];
    float* out = (float*)d_out;

    lstm_fused_kernel<<<2 * 128, 256>>>(x, Wih_f, Whh_f, bih_f, bhh_f,
                                        Wih_b, Whh_b, bih_b, bhh_b);
    head_kernel<<<(Bx * Tx) / 128, 256>>>(W1, b1, W2, b2, out);
}

// round 12
// speedup vs baseline: 1.3247x; 1.0114x over previous
#include <cuda_runtime.h>
#include <cstdint>

// Problem constants
#define Bx 256
#define Tx 3000
#define Ix 40
#define Hx 64
#define Gx 256        // 4*H gates
#define RCH 8         // recurrent x_proj chunk steps (3000 % 8 == 0 -> 375 chunks)
#define XTK 50        // xproj tokens per block (3000 % 50 == 0)

// Scratch (allocation-free rule: __device__ globals)
__device__ float g_h[2][(size_t)Bx * Tx * Hx];    // per-direction hidden outputs
__device__ float g_xp[2][(size_t)Bx * Tx * Gx];   // input projections (+biases); dir1 time-reversed

// ---------- packed f32x2 helpers ----------
union F2U { float2 f; unsigned long long u; };

__device__ __forceinline__ void ffma2(unsigned long long& acc,
                                      unsigned long long a,
                                      unsigned long long b) {
    asm("fma.rn.f32x2 %0, %1, %2, %0;" : "+l"(acc) : "l"(a), "l"(b));
}
__device__ __forceinline__ unsigned long long fadd2(unsigned long long a, unsigned long long b) {
    unsigned long long r;
    asm("add.rn.f32x2 %0, %1, %2;" : "=l"(r) : "l"(a), "l"(b));
    return r;
}
__device__ __forceinline__ float fsigmoid(float x) {
    return __fdividef(1.0f, 1.0f + __expf(-x));
}
__device__ __forceinline__ float ftanh_fast(float x) {
    return 1.0f - __fdividef(2.0f, __expf(2.0f * x) + 1.0f);
}
__device__ __forceinline__ float hsum2(unsigned long long a, unsigned long long b) {
    F2U s; s.u = fadd2(a, b);
    return s.f.x + s.f.y;
}

// ---------- cp.async helpers ----------
__device__ __forceinline__ unsigned int smem_u32(const void* p) {
    return (unsigned int)__cvta_generic_to_shared(p);
}
__device__ __forceinline__ void cp_async16(unsigned int s, const void* g) {
    asm volatile("cp.async.cg.shared.global [%0], [%1], 16;" :: "r"(s), "l"(g));
}
#define CP_COMMIT() asm volatile("cp.async.commit_group;")
#define CP_WAIT1()  asm volatile("cp.async.wait_group 1;")

// ================= x-projection kernel (R5-exact, measured 822us) =================
// Both directions per block; thread g holds W_ih rows for dir0/dir1.
// Unrolled by 2 tokens; dir1 output stored time-reversed.
__global__ __launch_bounds__(256, 2)
void xproj_kernel(const float* __restrict__ x,
                  const float* __restrict__ WihF, const float* __restrict__ bihF,
                  const float* __restrict__ bhhF,
                  const float* __restrict__ WihB, const float* __restrict__ bihB,
                  const float* __restrict__ bhhB)
{
    const int g = threadIdx.x;
    __shared__ __align__(16) float sx[XTK * Ix];   // 8 KB

    unsigned long long wf[20], wb[20];
    {
        const float2* wrf = (const float2*)(WihF + (size_t)g * Ix);
        const float2* wrb = (const float2*)(WihB + (size_t)g * Ix);
        #pragma unroll
        for (int j = 0; j < 20; j++) { F2U u; u.f = wrf[j]; wf[j] = u.u; }
        #pragma unroll
        for (int j = 0; j < 20; j++) { F2U u; u.f = wrb[j]; wb[j] = u.u; }
    }
    const float biasF = bihF[g] + bhhF[g];
    const float biasB = bihB[g] + bhhB[g];

    const int tiles_per_b = Tx / XTK;
    const int batch = blockIdx.x / tiles_per_b;
    const int trel  = (blockIdx.x % tiles_per_b) * XTK;

    {
        const float4* xs = (const float4*)(x + ((size_t)batch * Tx + trel) * Ix);
        float4* sd = (float4*)sx;
        #pragma unroll
        for (int i = 0; i < 2; i++) {
            int idx = threadIdx.x + i * 256;
            if (idx < XTK * Ix / 4) sd[idx] = xs[idx];
        }
    }
    __syncthreads();

    float* pF = g_xp[0] + ((size_t)batch * Tx + trel) * Gx + g;
    float* pB = g_xp[1] + ((size_t)batch * Tx + (Tx - 1 - trel)) * Gx + g;
    const ulonglong2* xr = (const ulonglong2*)sx;

    #pragma unroll 1
    for (int k = 0; k < XTK / 2; k++) {
        F2U fa0, fa1, ba0, ba1, fb0, fb1, bb0, bb1;
        fa0.f = make_float2(biasF, 0.0f); fa1.f = make_float2(0.0f, 0.0f);
        ba0.f = make_float2(biasB, 0.0f); ba1.f = make_float2(0.0f, 0.0f);
        fb0 = fa0; fb1 = fa1; bb0 = ba0; bb1 = ba1;
        #pragma unroll
        for (int j = 0; j < 10; j++) {
            const ulonglong2 ua = xr[j];            // token 2k
            const ulonglong2 ub = xr[10 + j];       // token 2k+1
            ffma2(fa0.u, ua.x, wf[2 * j]);  ffma2(fa1.u, ua.y, wf[2 * j + 1]);
            ffma2(ba0.u, ua.x, wb[2 * j]);  ffma2(ba1.u, ua.y, wb[2 * j + 1]);
            ffma2(fb0.u, ub.x, wf[2 * j]);  ffma2(fb1.u, ub.y, wf[2 * j + 1]);
            ffma2(bb0.u, ub.x, wb[2 * j]);  ffma2(bb1.u, ub.y, wb[2 * j + 1]);
        }
        xr += 20;
        pF[0]   = hsum2(fa0.u, fa1.u);
        pF[Gx]  = hsum2(fb0.u, fb1.u);
        pB[0]   = hsum2(ba0.u, ba1.u);
        pB[-Gx] = hsum2(bb0.u, bb1.u);
        pF += 2 * Gx;
        pB -= 2 * Gx;
    }
}

// ================= recurrent LSTM kernel (R3-exact, measured ~2083us) =================
// 256 blocks; block handles 2 sequences (batches 2p, 2p+1) of one direction.
// Thread g: gate g for BOTH sequences (shared W_hh row in regs).
__global__ __launch_bounds__(256, 2)
void lstm_kernel(const float* __restrict__ Whh_f, const float* __restrict__ Whh_b)
{
    const int dir   = blockIdx.x & 1;
    const int bpair = blockIdx.x >> 1;          // 0..127
    const int bA    = 2 * bpair;

    const float* Whh = dir ? Whh_b : Whh_f;
    float* hout = g_h[dir];
    const float* xpA = g_xp[dir] + (size_t)bA * Tx * Gx;
    const float* xpB = xpA + (size_t)Tx * Gx;

    const int g = threadIdx.x;

    __shared__ __align__(16) float sxp[2][2][RCH * Gx];  // [seq][buf] 32 KB
    __shared__ __align__(16) float sh[2][Hx];
    __shared__ float sgates[2][Gx];

    // W_hh row (64 floats = 32 f32x2) in registers, shared by both sequences
    unsigned long long whh[32];
    {
        const float2* wr = (const float2*)(Whh + (size_t)g * Hx);
        #pragma unroll
        for (int j = 0; j < 32; j++) { F2U u; u.f = wr[j]; whh[j] = u.u; }
    }

    if (g < 128) sh[g >> 6][g & 63] = 0.0f;
    float c = 0.0f;                       // c for (seq=(g>>6)&1, idx=g&63), 2x redundant
    const int region = g >> 6;            // warp-uniform gate type
    const int us  = (g >> 6) & 1;         // update seq
    const int uix = g & 63;               // update h index

    // prefetch chunk 0 for both seqs (2 segs per thread per seq)
    {
        unsigned int sA = smem_u32(&sxp[0][0][0]) + threadIdx.x * 16;
        unsigned int sB = smem_u32(&sxp[1][0][0]) + threadIdx.x * 16;
        const char* gA = (const char*)xpA + threadIdx.x * 16;
        const char* gB = (const char*)xpB + threadIdx.x * 16;
        cp_async16(sA, gA); cp_async16(sA + 4096, gA + 4096);
        cp_async16(sB, gB); cp_async16(sB + 4096, gB + 4096);
        CP_COMMIT();
    }
    __syncthreads();

    const int NCH = Tx / RCH;
    for (int ck = 0; ck < NCH; ck++) {
        // prefetch next chunk into the other buffer
        if (ck + 1 < NCH) {
            const int nb = (ck + 1) & 1;
            unsigned int sA = smem_u32(&sxp[0][nb][0]) + threadIdx.x * 16;
            unsigned int sB = smem_u32(&sxp[1][nb][0]) + threadIdx.x * 16;
            const char* gA = (const char*)(xpA + (size_t)(ck + 1) * RCH * Gx) + threadIdx.x * 16;
            const char* gB = (const char*)(xpB + (size_t)(ck + 1) * RCH * Gx) + threadIdx.x * 16;
            cp_async16(sA, gA); cp_async16(sA + 4096, gA + 4096);
            cp_async16(sB, gB); cp_async16(sB + 4096, gB + 4096);
        }
        CP_COMMIT();
        CP_WAIT1();
        __syncthreads();

        const int cb = ck & 1;
        const float* xbA = sxp[0][cb];
        const float* xbB = sxp[1][cb];

        for (int si = 0; si < RCH; si++) {
            const float xvA = xbA[si * Gx + g];
            const float xvB = xbB[si * Gx + g];

            F2U aA0, aA1, aB0, aB1;
            aA0.f = make_float2(xvA, 0.0f);
            aB0.f = make_float2(xvB, 0.0f);
            aA1.f = make_float2(0.0f, 0.0f);
            aB1 = aA1;

            const ulonglong2* hA = (const ulonglong2*)sh[0];  // LDS.128 broadcast
            const ulonglong2* hB = (const ulonglong2*)sh[1];
            #pragma unroll
            for (int j = 0; j < 16; j++) {
                const ulonglong2 ua = hA[j];
                const ulonglong2 ub = hB[j];
                ffma2(aA0.u, ua.x, whh[2 * j]);
                ffma2(aA1.u, ua.y, whh[2 * j + 1]);
                ffma2(aB0.u, ub.x, whh[2 * j]);
                ffma2(aB1.u, ub.y, whh[2 * j + 1]);
            }
            const float vA = hsum2(aA0.u, aA1.u);
            const float vB = hsum2(aB0.u, aB1.u);

            if (region == 2) {
                sgates[0][g] = ftanh_fast(vA);
                sgates[1][g] = ftanh_fast(vB);
            } else {
                sgates[0][g] = fsigmoid(vA);
                sgates[1][g] = fsigmoid(vB);
            }
            __syncthreads();

            // all 256 threads update (2x redundant per (seq,idx); benign same-value race)
            {
                const float ig = sgates[us][uix];
                const float fg = sgates[us][64 + uix];
                const float gg = sgates[us][128 + uix];
                const float og = sgates[us][192 + uix];
                c = fg * c + ig * gg;
                const float h = og * ftanh_fast(c);
                sh[us][uix] = h;
                if (g < 128) {
                    const int srel = ck * RCH + si;
                    const int t = dir ? (Tx - 1 - srel) : srel;
                    hout[((size_t)(bA + us) * Tx + t) * Hx + uix] = h;
                }
            }
            __syncthreads();
        }
    }
}

// ================= MLP head kernel v2 =================
// 4 lanes per token (quarter-split: lane q of each 4-lane group owns 32 of the
// 128 h dims). W1 staged in SMEM with bank-disjoint padded layout (row = 144
// floats, quarter stride 36) -> per-o read = 8 conflict-free LDS.128.
// ~60 regs -> high occupancy. Combine via 2 shfl_xor; all 4 lanes redundant.
__global__ __launch_bounds__(256, 3)
void head_kernel(const float* __restrict__ W1, const float* __restrict__ b1,
                 const float* __restrict__ W2, const float* __restrict__ b2,
                 float* __restrict__ out)
{
    __shared__ __align__(16) float sW1[64 * 144];  // 36 KB, padded
    __shared__ float sb1[64];
    __shared__ float sW2[64];

    const int tid = threadIdx.x;
    // load W1 into padded layout: quarter q of row o at sW1[o*144 + q*36]
    for (int i = tid; i < 64 * 32; i += 256) {     // i indexes float4 of W1
        const int o  = i >> 5;
        const int j  = i & 31;                     // float4 within row (0..31)
        const int q  = j >> 3;                     // quarter 0..3
        const int wi = j & 7;                      // float4 within quarter
        ((float4*)sW1)[o * 36 + q * 9 + wi] = ((const float4*)W1)[i];
    }
    if (tid < 64) { sb1[tid] = b1[tid]; sW2[tid] = W2[tid]; }
    __syncthreads();
    const float bias2 = b2[0];

    const size_t tok = (size_t)blockIdx.x * 64 + (tid >> 2);
    const int q = tid & 3;                         // quarter: 0,1 = hf halves; 2,3 = hb halves

    // this lane's 32 h floats as 16 packed u64
    unsigned long long hreg[16];
    {
        const ulonglong2* hv =
            (const ulonglong2*)(g_h[q >> 1] + tok * Hx + (q & 1) * 32);
        #pragma unroll
        for (int j = 0; j < 8; j++) {
            ulonglong2 u = hv[j];
            hreg[2 * j] = u.x; hreg[2 * j + 1] = u.y;
        }
    }

    float acc = bias2;
    #pragma unroll 2
    for (int o = 0; o < 64; o++) {
        const ulonglong2* w = (const ulonglong2*)(sW1 + o * 144 + q * 36);
        F2U a0, a1;
        a0.f = make_float2(0.0f, 0.0f);
        a1 = a0;
        #pragma unroll
        for (int j = 0; j < 4; j++) {
            const ulonglong2 w0 = w[2 * j];
            const ulonglong2 w1 = w[2 * j + 1];
            ffma2(a0.u, hreg[4 * j],     w0.x);
            ffma2(a1.u, hreg[4 * j + 1], w0.y);
            ffma2(a0.u, hreg[4 * j + 2], w1.x);
            ffma2(a1.u, hreg[4 * j + 3], w1.y);
        }
        float v = hsum2(a0.u, a1.u);
        v += __shfl_xor_sync(0xffffffffu, v, 1);   // combine quarters
        v += __shfl_xor_sync(0xffffffffu, v, 2);
        const float z = fmaxf(v + sb1[o], 0.0f);
        acc = fmaf(z, sW2[o], acc);
    }
    if (q == 0) out[tok] = fsigmoid(acc);
}

// ================= launch =================
extern "C" void kernel_launch(void* const* d_in, const int* in_sizes, int n_in,
                              void* d_out, int out_size)
{
    const float* x     = (const float*)d_in[0];
    const float* Wih_f = (const float*)d_in[1];
    const float* Whh_f = (const float*)d_in[2];
    const float* bih_f = (const float*)d_in[3];
    const float* bhh_f = (const float*)d_in[4];
    const float* Wih_b = (const float*)d_in[5];
    const float* Whh_b = (const float*)d_in[6];
    const float* bih_b = (const float*)d_in[7];
    const float* bhh_b = (const float*)d_in[8];
    const float* W1    = (const float*)d_in[9];
    const float* b1    = (const float*)d_in[10];
    const float* W2    = (const float*)d_in[11];
    const float* b2    = (const float*)d_in[12];
    float* out = (float*)d_out;

    xproj_kernel<<<Bx * (Tx / XTK), 256>>>(x, Wih_f, bih_f, bhh_f, Wih_b, bih_b, bhh_b);
    lstm_kernel<<<Bx, 256>>>(Whh_f, Whh_b);          // R3-exact recurrence
    head_kernel<<<(Bx * Tx) / 64, 256>>>(W1, b1, W2, b2, out);
}

// round 13
// speedup vs baseline: 1.5703x; 1.1853x over previous
#include <cuda_runtime.h>
#include <cstdint>

// Problem constants
#define Bx 256
#define Tx 3000
#define Ix 40
#define Hx 64
#define Gx 256        // 4*H gates
#define RCH 8         // recurrent x_proj chunk steps (3000 % 8 == 0 -> 375 chunks)
#define XTK 50        // xproj tokens per block (3000 % 50 == 0)

// Scratch (allocation-free rule: __device__ globals)
__device__ float g_h[2][(size_t)Bx * Tx * Hx];    // per-direction hidden outputs
__device__ float g_xp[2][(size_t)Bx * Tx * Gx];   // input projections (+biases); dir1 time-reversed

// ---------- packed f32x2 helpers ----------
union F2U { float2 f; unsigned long long u; };

__device__ __forceinline__ void ffma2(unsigned long long& acc,
                                      unsigned long long a,
                                      unsigned long long b) {
    asm("fma.rn.f32x2 %0, %1, %2, %0;" : "+l"(acc) : "l"(a), "l"(b));
}
__device__ __forceinline__ unsigned long long fadd2(unsigned long long a, unsigned long long b) {
    unsigned long long r;
    asm("add.rn.f32x2 %0, %1, %2;" : "=l"(r) : "l"(a), "l"(b));
    return r;
}
__device__ __forceinline__ float fsigmoid(float x) {
    return __fdividef(1.0f, 1.0f + __expf(-x));
}
__device__ __forceinline__ float ftanh_fast(float x) {
    return 1.0f - __fdividef(2.0f, __expf(2.0f * x) + 1.0f);
}
__device__ __forceinline__ float hsum2(unsigned long long a, unsigned long long b) {
    F2U s; s.u = fadd2(a, b);
    return s.f.x + s.f.y;
}

// ---------- cp.async helpers ----------
__device__ __forceinline__ unsigned int smem_u32(const void* p) {
    return (unsigned int)__cvta_generic_to_shared(p);
}
__device__ __forceinline__ void cp_async16(unsigned int s, const void* g) {
    asm volatile("cp.async.cg.shared.global [%0], [%1], 16;" :: "r"(s), "l"(g));
}
#define CP_COMMIT() asm volatile("cp.async.commit_group;")
#define CP_WAIT1()  asm volatile("cp.async.wait_group 1;")

// ================= x-projection kernel (R5-exact, measured 822us) =================
// Both directions per block; thread g holds W_ih rows for dir0/dir1.
// Unrolled by 2 tokens; dir1 output stored time-reversed.
__global__ __launch_bounds__(256, 2)
void xproj_kernel(const float* __restrict__ x,
                  const float* __restrict__ WihF, const float* __restrict__ bihF,
                  const float* __restrict__ bhhF,
                  const float* __restrict__ WihB, const float* __restrict__ bihB,
                  const float* __restrict__ bhhB)
{
    const int g = threadIdx.x;
    __shared__ __align__(16) float sx[XTK * Ix];   // 8 KB

    unsigned long long wf[20], wb[20];
    {
        const float2* wrf = (const float2*)(WihF + (size_t)g * Ix);
        const float2* wrb = (const float2*)(WihB + (size_t)g * Ix);
        #pragma unroll
        for (int j = 0; j < 20; j++) { F2U u; u.f = wrf[j]; wf[j] = u.u; }
        #pragma unroll
        for (int j = 0; j < 20; j++) { F2U u; u.f = wrb[j]; wb[j] = u.u; }
    }
    const float biasF = bihF[g] + bhhF[g];
    const float biasB = bihB[g] + bhhB[g];

    const int tiles_per_b = Tx / XTK;
    const int batch = blockIdx.x / tiles_per_b;
    const int trel  = (blockIdx.x % tiles_per_b) * XTK;

    {
        const float4* xs = (const float4*)(x + ((size_t)batch * Tx + trel) * Ix);
        float4* sd = (float4*)sx;
        #pragma unroll
        for (int i = 0; i < 2; i++) {
            int idx = threadIdx.x + i * 256;
            if (idx < XTK * Ix / 4) sd[idx] = xs[idx];
        }
    }
    __syncthreads();

    float* pF = g_xp[0] + ((size_t)batch * Tx + trel) * Gx + g;
    float* pB = g_xp[1] + ((size_t)batch * Tx + (Tx - 1 - trel)) * Gx + g;
    const ulonglong2* xr = (const ulonglong2*)sx;

    #pragma unroll 1
    for (int k = 0; k < XTK / 2; k++) {
        F2U fa0, fa1, ba0, ba1, fb0, fb1, bb0, bb1;
        fa0.f = make_float2(biasF, 0.0f); fa1.f = make_float2(0.0f, 0.0f);
        ba0.f = make_float2(biasB, 0.0f); ba1.f = make_float2(0.0f, 0.0f);
        fb0 = fa0; fb1 = fa1; bb0 = ba0; bb1 = ba1;
        #pragma unroll
        for (int j = 0; j < 10; j++) {
            const ulonglong2 ua = xr[j];            // token 2k
            const ulonglong2 ub = xr[10 + j];       // token 2k+1
            ffma2(fa0.u, ua.x, wf[2 * j]);  ffma2(fa1.u, ua.y, wf[2 * j + 1]);
            ffma2(ba0.u, ua.x, wb[2 * j]);  ffma2(ba1.u, ua.y, wb[2 * j + 1]);
            ffma2(fb0.u, ub.x, wf[2 * j]);  ffma2(fb1.u, ub.y, wf[2 * j + 1]);
            ffma2(bb0.u, ub.x, wb[2 * j]);  ffma2(bb1.u, ub.y, wb[2 * j + 1]);
        }
        xr += 20;
        pF[0]   = hsum2(fa0.u, fa1.u);
        pF[Gx]  = hsum2(fb0.u, fb1.u);
        pB[0]   = hsum2(ba0.u, ba1.u);
        pB[-Gx] = hsum2(bb0.u, bb1.u);
        pF += 2 * Gx;
        pB -= 2 * Gx;
    }
}

// ================= recurrent LSTM kernel (R3 + phase-2 guard) =================
// 256 blocks; block handles 2 sequences (batches 2p, 2p+1) of one direction.
// Thread g: gate g for BOTH sequences (shared W_hh row in regs).
// Phase 2 now guarded to g<128 (warps 4-7 previously duplicated it exactly).
__global__ __launch_bounds__(256, 2)
void lstm_kernel(const float* __restrict__ Whh_f, const float* __restrict__ Whh_b)
{
    const int dir   = blockIdx.x & 1;
    const int bpair = blockIdx.x >> 1;          // 0..127
    const int bA    = 2 * bpair;

    const float* Whh = dir ? Whh_b : Whh_f;
    float* hout = g_h[dir];
    const float* xpA = g_xp[dir] + (size_t)bA * Tx * Gx;
    const float* xpB = xpA + (size_t)Tx * Gx;

    const int g = threadIdx.x;

    __shared__ __align__(16) float sxp[2][2][RCH * Gx];  // [seq][buf] 32 KB
    __shared__ __align__(16) float sh[2][Hx];
    __shared__ float sgates[2][Gx];

    // W_hh row (64 floats = 32 f32x2) in registers, shared by both sequences
    unsigned long long whh[32];
    {
        const float2* wr = (const float2*)(Whh + (size_t)g * Hx);
        #pragma unroll
        for (int j = 0; j < 32; j++) { F2U u; u.f = wr[j]; whh[j] = u.u; }
    }

    if (g < 128) sh[g >> 6][g & 63] = 0.0f;
    float c = 0.0f;                       // phase-2 state (g < 128)
    const int region = g >> 6;            // warp-uniform gate type
    const int us  = (g >> 6) & 1;         // update seq (g < 128)
    const int uix = g & 63;               // update h index

    // prefetch chunk 0 for both seqs (2 segs per thread per seq)
    {
        unsigned int sA = smem_u32(&sxp[0][0][0]) + threadIdx.x * 16;
        unsigned int sB = smem_u32(&sxp[1][0][0]) + threadIdx.x * 16;
        const char* gA = (const char*)xpA + threadIdx.x * 16;
        const char* gB = (const char*)xpB + threadIdx.x * 16;
        cp_async16(sA, gA); cp_async16(sA + 4096, gA + 4096);
        cp_async16(sB, gB); cp_async16(sB + 4096, gB + 4096);
        CP_COMMIT();
    }
    __syncthreads();

    const int NCH = Tx / RCH;
    for (int ck = 0; ck < NCH; ck++) {
        // prefetch next chunk into the other buffer
        if (ck + 1 < NCH) {
            const int nb = (ck + 1) & 1;
            unsigned int sA = smem_u32(&sxp[0][nb][0]) + threadIdx.x * 16;
            unsigned int sB = smem_u32(&sxp[1][nb][0]) + threadIdx.x * 16;
            const char* gA = (const char*)(xpA + (size_t)(ck + 1) * RCH * Gx) + threadIdx.x * 16;
            const char* gB = (const char*)(xpB + (size_t)(ck + 1) * RCH * Gx) + threadIdx.x * 16;
            cp_async16(sA, gA); cp_async16(sA + 4096, gA + 4096);
            cp_async16(sB, gB); cp_async16(sB + 4096, gB + 4096);
        }
        CP_COMMIT();
        CP_WAIT1();
        __syncthreads();

        const int cb = ck & 1;
        const float* xbA = sxp[0][cb];
        const float* xbB = sxp[1][cb];

        for (int si = 0; si < RCH; si++) {
            const float xvA = xbA[si * Gx + g];
            const float xvB = xbB[si * Gx + g];

            F2U aA0, aA1, aB0, aB1;
            aA0.f = make_float2(xvA, 0.0f);
            aB0.f = make_float2(xvB, 0.0f);
            aA1.f = make_float2(0.0f, 0.0f);
            aB1 = aA1;

            const ulonglong2* hA = (const ulonglong2*)sh[0];  // LDS.128 broadcast
            const ulonglong2* hB = (const ulonglong2*)sh[1];
            #pragma unroll
            for (int j = 0; j < 16; j++) {
                const ulonglong2 ua = hA[j];
                const ulonglong2 ub = hB[j];
                ffma2(aA0.u, ua.x, whh[2 * j]);
                ffma2(aA1.u, ua.y, whh[2 * j + 1]);
                ffma2(aB0.u, ub.x, whh[2 * j]);
                ffma2(aB1.u, ub.y, whh[2 * j + 1]);
            }
            const float vA = hsum2(aA0.u, aA1.u);
            const float vB = hsum2(aB0.u, aB1.u);

            if (region == 2) {
                sgates[0][g] = ftanh_fast(vA);
                sgates[1][g] = ftanh_fast(vB);
            } else {
                sgates[0][g] = fsigmoid(vA);
                sgates[1][g] = fsigmoid(vB);
            }
            __syncthreads();

            // ---- phase 2 (guarded): threads 0..127 cover (seq 0/1, idx 0..63) ----
            if (g < 128) {
                const float ig = sgates[us][uix];
                const float fg = sgates[us][64 + uix];
                const float gg = sgates[us][128 + uix];
                const float og = sgates[us][192 + uix];
                c = fg * c + ig * gg;
                const float h = og * ftanh_fast(c);
                sh[us][uix] = h;
                const int srel = ck * RCH + si;
                const int t = dir ? (Tx - 1 - srel) : srel;
                hout[((size_t)(bA + us) * Tx + t) * Hx + uix] = h;
            }
            __syncthreads();
        }
    }
}

// ================= MLP head kernel (R1-exact, measured 567us) =================
// one thread per token, W1 broadcast from SMEM, h in registers, 4 f32x2 chains.
__global__ __launch_bounds__(256, 1)
void head_kernel(const float* __restrict__ W1, const float* __restrict__ b1,
                 const float* __restrict__ W2, const float* __restrict__ b2,
                 float* __restrict__ out)
{
    __shared__ __align__(16) float sW1[64 * 128];  // 32 KB
    __shared__ float sb1[64];
    __shared__ float sW2[64];
    __shared__ float sb2;

    const int tid = threadIdx.x;
    for (int i = tid; i < 64 * 128; i += 256) sW1[i] = W1[i];
    if (tid < 64) { sb1[tid] = b1[tid]; sW2[tid] = W2[tid]; }
    if (tid == 0) sb2 = b2[0];
    __syncthreads();

    const size_t tok = (size_t)blockIdx.x * 256 + tid;

    // load h = [hf(64) ; hb(64)] into registers as 64 packed f32x2
    unsigned long long hreg[64];
    {
        const float2* pf = (const float2*)(g_h[0] + tok * Hx);
        const float2* pb = (const float2*)(g_h[1] + tok * Hx);
        #pragma unroll
        for (int j = 0; j < 32; j++) { F2U u; u.f = pf[j]; hreg[j] = u.u; }
        #pragma unroll
        for (int j = 0; j < 32; j++) { F2U u; u.f = pb[j]; hreg[32 + j] = u.u; }
    }

    float acc_out = sb2;
    for (int o = 0; o < 64; o++) {
        F2U a0, a1, a2, a3;
        a0.f = make_float2(sb1[o], 0.0f);
        a1.f = make_float2(0.0f, 0.0f);
        a2.f = a1.f; a3.f = a1.f;
        const ulonglong2* w = (const ulonglong2*)(sW1 + o * 128);  // 16B LDS, broadcast
        #pragma unroll
        for (int j = 0; j < 16; j++) {
            const ulonglong2 wv0 = w[2 * j];
            const ulonglong2 wv1 = w[2 * j + 1];
            ffma2(a0.u, hreg[4 * j + 0], wv0.x);
            ffma2(a1.u, hreg[4 * j + 1], wv0.y);
            ffma2(a2.u, hreg[4 * j + 2], wv1.x);
            ffma2(a3.u, hreg[4 * j + 3], wv1.y);
        }
        float z = (a0.f.x + a0.f.y) + (a1.f.x + a1.f.y)
                + (a2.f.x + a2.f.y) + (a3.f.x + a3.f.y);
        z = fmaxf(z, 0.0f);
        acc_out = fmaf(z, sW2[o], acc_out);
    }
    out[tok] = fsigmoid(acc_out);
}

// ================= launch =================
extern "C" void kernel_launch(void* const* d_in, const int* in_sizes, int n_in,
                              void* d_out, int out_size)
{
    const float* x     = (const float*)d_in[0];
    const float* Wih_f = (const float*)d_in[1];
    const float* Whh_f = (const float*)d_in[2];
    const float* bih_f = (const float*)d_in[3];
    const float* bhh_f = (const float*)d_in[4];
    const float* Wih_b = (const float*)d_in[5];
    const float* Whh_b = (const float*)d_in[6];
    const float* bih_b = (const float*)d_in[7];
    const float* bhh_b = (const float*)d_in[8];
    const float* W1    = (const float*)d_in[9];
    const float* b1    = (const float*)d_in[10];
    const float* W2    = (const float*)d_in[11];
    const float* b2    = (const float*)d_in[12];
    float* out = (float*)d_out;

    xproj_kernel<<<Bx * (Tx / XTK), 256>>>(x, Wih_f, bih_f, bhh_f, Wih_b, bih_b, bhh_b);
    lstm_kernel<<<Bx, 256>>>(Whh_f, Whh_b);          // R3 recurrence + phase-2 guard
    head_kernel<<<(Bx * Tx) / 256, 256>>>(W1, b1, W2, b2, out);
}